// round 15
// baseline (speedup 1.0000x reference)
#include <cuda_runtime.h>
#include <cuda_fp16.h>
#include <stdint.h>

#define BATCHN 65536
#define NROWS  (BATCHN * 8)
#define NGRP   8192
#define OBSD   114

__device__ __half g_av[(size_t)BATCHN * 128];   // agent values, fp16 (16 MB)

__device__ __forceinline__ float fast_tanh(float x){float y;asm("tanh.approx.f32 %0,%1;":"=f"(y):"f"(x));return y;}
__device__ __forceinline__ float tanh_acc(float x){ return 1.f - __fdividef(2.f, __expf(2.f * x) + 1.f); }
__device__ __forceinline__ uint32_t pack2(float a, float b){ __half2 h = __floats2half2_rn(a, b); return *(uint32_t*)&h; }

__device__ __forceinline__ void mma16(float c[4], uint32_t a0, uint32_t a1, uint32_t a2, uint32_t a3,
                                      uint32_t b0, uint32_t b1){
    asm volatile("mma.sync.aligned.m16n8k16.row.col.f32.f16.f16.f32 "
                 "{%0,%1,%2,%3},{%4,%5,%6,%7},{%8,%9},{%0,%1,%2,%3};"
                 : "+f"(c[0]), "+f"(c[1]), "+f"(c[2]), "+f"(c[3])
                 : "r"(a0), "r"(a1), "r"(a2), "r"(a3), "r"(b0), "r"(b1));
}

// ============================================================================
// Dual-slab layer in 4 column-quarter passes. Each uint4 B-fragment feeds
// 4 MMAs (2 slabs x 2 nt) -> weight LDS per row is HALF of single-slab.
// acc per pass = 2x4x4 = 32 regs. Transition per quarter writes
// afout[s][2q], afout[s][2q+1] (D-frag == next A-frag identity).
// ============================================================================
template<int KS>
__device__ __forceinline__ void layer_dual(const uint32_t afin[2][KS][4],
                                           const uint4* __restrict__ Wp,
                                           uint32_t afout[2][8][4],
                                           const float* __restrict__ bias,
                                           int t, int lane){
    #pragma unroll
    for (int q = 0; q < 4; q++){
        float acc[2][4][4];
        #pragma unroll
        for (int s = 0; s < 2; s++)
            #pragma unroll
            for (int j = 0; j < 4; j++)
                acc[s][j][0]=acc[s][j][1]=acc[s][j][2]=acc[s][j][3]=0.f;
        #pragma unroll
        for (int ks = 0; ks < KS; ks++){
            uint4 b0 = Wp[ks * 256 + (2*q)     * 32 + lane];
            uint4 b1 = Wp[ks * 256 + (2*q + 1) * 32 + lane];
            #pragma unroll
            for (int s = 0; s < 2; s++){
                mma16(acc[s][0], afin[s][ks][0], afin[s][ks][1], afin[s][ks][2], afin[s][ks][3], b0.x, b0.y);
                mma16(acc[s][1], afin[s][ks][0], afin[s][ks][1], afin[s][ks][2], afin[s][ks][3], b0.z, b0.w);
                mma16(acc[s][2], afin[s][ks][0], afin[s][ks][1], afin[s][ks][2], afin[s][ks][3], b1.x, b1.y);
                mma16(acc[s][3], afin[s][ks][0], afin[s][ks][1], afin[s][ks][2], afin[s][ks][3], b1.z, b1.w);
            }
        }
        // transition quarter -> afout[s][2q], afout[s][2q+1]
        #pragma unroll
        for (int s = 0; s < 2; s++){
            #pragma unroll
            for (int h = 0; h < 2; h++){       // h: which ks_out within quarter
                int c0 = (4*q + 2*h)     * 8 + 2 * t;
                int c1 = (4*q + 2*h + 1) * 8 + 2 * t;
                float b00 = bias[c0], b01 = bias[c0 + 1];
                float b10 = bias[c1], b11 = bias[c1 + 1];
                afout[s][2*q + h][0] = pack2(fast_tanh(acc[s][2*h][0] + b00),   fast_tanh(acc[s][2*h][1] + b01));
                afout[s][2*q + h][1] = pack2(fast_tanh(acc[s][2*h][2] + b00),   fast_tanh(acc[s][2*h][3] + b01));
                afout[s][2*q + h][2] = pack2(fast_tanh(acc[s][2*h+1][0] + b10), fast_tanh(acc[s][2*h+1][1] + b11));
                afout[s][2*q + h][3] = pack2(fast_tanh(acc[s][2*h+1][2] + b10), fast_tanh(acc[s][2*h+1][3] + b11));
            }
        }
    }
}

// Final layer: same quarter structure, but epilogue = tanh_acc + weighted
// neighbor-sum (g-dim shuffle reduce) + direct AA writes.
__device__ __forceinline__ void layer_dual_combine(const uint32_t afin[2][8][4],
                                                   const uint4* __restrict__ Wp,
                                                   const float* __restrict__ bias,
                                                   const float wA[2], const float wB[2],
                                                   float* __restrict__ AA, int pair,
                                                   int t, int lane){
    #pragma unroll
    for (int q = 0; q < 4; q++){
        float acc[2][4][4];
        #pragma unroll
        for (int s = 0; s < 2; s++)
            #pragma unroll
            for (int j = 0; j < 4; j++)
                acc[s][j][0]=acc[s][j][1]=acc[s][j][2]=acc[s][j][3]=0.f;
        #pragma unroll
        for (int ks = 0; ks < 8; ks++){
            uint4 b0 = Wp[ks * 256 + (2*q)     * 32 + lane];
            uint4 b1 = Wp[ks * 256 + (2*q + 1) * 32 + lane];
            #pragma unroll
            for (int s = 0; s < 2; s++){
                mma16(acc[s][0], afin[s][ks][0], afin[s][ks][1], afin[s][ks][2], afin[s][ks][3], b0.x, b0.y);
                mma16(acc[s][1], afin[s][ks][0], afin[s][ks][1], afin[s][ks][2], afin[s][ks][3], b0.z, b0.w);
                mma16(acc[s][2], afin[s][ks][0], afin[s][ks][1], afin[s][ks][2], afin[s][ks][3], b1.x, b1.y);
                mma16(acc[s][3], afin[s][ks][0], afin[s][ks][1], afin[s][ks][2], afin[s][ks][3], b1.z, b1.w);
            }
        }
        #pragma unroll
        for (int s = 0; s < 2; s++){
            #pragma unroll
            for (int j = 0; j < 4; j++){
                int c = (4*q + j) * 8 + 2 * t;
                float b0 = bias[c], b1 = bias[c + 1];
                float a0 = tanh_acc(acc[s][j][0] + b0) * wA[s];
                float a1 = tanh_acc(acc[s][j][1] + b1) * wA[s];
                float e0 = tanh_acc(acc[s][j][2] + b0) * wB[s];
                float e1 = tanh_acc(acc[s][j][3] + b1) * wB[s];
                #pragma unroll
                for (int o = 4; o <= 16; o <<= 1){
                    a0 += __shfl_xor_sync(0xffffffff, a0, o);
                    a1 += __shfl_xor_sync(0xffffffff, a1, o);
                    e0 += __shfl_xor_sync(0xffffffff, e0, o);
                    e1 += __shfl_xor_sync(0xffffffff, e1, o);
                }
                float* outA = AA + (size_t)((pair * 2 + s) * 2) * 128;
                if (lane < 4)      *(float2*)(outA + (4*q + j) * 8 + 2 * lane)             = make_float2(a0, a1);
                else if (lane < 8) *(float2*)(outA + 128 + (4*q + j) * 8 + 2 * (lane & 3)) = make_float2(e0, e1);
            }
        }
    }
}

// Pack W[k][n] (row-major K x 128 fp32) into uint4 B-fragment-pair order.
__device__ __forceinline__ void pack_w4(const float* __restrict__ W, uint4* __restrict__ Wp,
                                        int KS, int K, int tid, int nthr){
    for (int f = tid; f < KS * 8 * 32; f += nthr){
        int ks = f >> 8, ntp = (f >> 5) & 7, lane = f & 31;
        int g = lane >> 2, t = lane & 3;
        int n0 = ntp * 16 + g, n1 = n0 + 8;
        int k0 = ks * 16 + 2 * t, k1 = k0 + 8;
        float a00 = (k0     < K) ? W[(size_t)k0       * 128 + n0] : 0.f;
        float a01 = (k0 + 1 < K) ? W[(size_t)(k0 + 1) * 128 + n0] : 0.f;
        float a10 = (k1     < K) ? W[(size_t)k1       * 128 + n0] : 0.f;
        float a11 = (k1 + 1 < K) ? W[(size_t)(k1 + 1) * 128 + n0] : 0.f;
        float b00 = (k0     < K) ? W[(size_t)k0       * 128 + n1] : 0.f;
        float b01 = (k0 + 1 < K) ? W[(size_t)(k0 + 1) * 128 + n1] : 0.f;
        float b10 = (k1     < K) ? W[(size_t)k1       * 128 + n1] : 0.f;
        float b11 = (k1 + 1 < K) ? W[(size_t)(k1 + 1) * 128 + n1] : 0.f;
        Wp[f] = make_uint4(pack2(a00, a01), pack2(a10, a11), pack2(b00, b01), pack2(b10, b11));
    }
}

// ---- Coalesced gather prefetch (one slab) ----
__device__ __forceinline__ void gather_pf(const float* __restrict__ obs, int slab, int lane,
                                          uint32_t ps[5], uint32_t pn[3]){
    const int base = slab * 16;
    #pragma unroll
    for (int k = 0; k < 4; k++){
        int i0 = (2*k) * 32 + lane, i1 = i0 + 32;
        float v0 = obs[(size_t)((base + i0 / 18) & (BATCHN - 1)) * OBSD + i0 % 18];
        float v1 = obs[(size_t)((base + i1 / 18) & (BATCHN - 1)) * OBSD + i1 % 18];
        ps[k] = pack2(v0, v1);
    }
    {
        int i0 = 8 * 32 + lane;
        float v0 = obs[(size_t)((base + i0 / 18) & (BATCHN - 1)) * OBSD + i0 % 18];
        ps[4] = pack2(v0, 0.f);
    }
    const float* nb = obs + (size_t)(slab * 2) * OBSD + 18;
    #pragma unroll
    for (int k = 0; k < 3; k++){
        int i0 = (2*k) * 32 + lane, i1 = i0 + 32;
        float v0 = (i0 < 96) ? nb[i0] : nb[OBSD + (i0 - 96)];
        float v1 = (i1 < 96) ? nb[i1] : nb[OBSD + (i1 - 96)];
        pn[k] = pack2(v0, v1);
    }
}

__device__ __forceinline__ void stage_store(__half* __restrict__ stg, int lane,
                                            const uint32_t ps[5], const uint32_t pn[3]){
    #pragma unroll
    for (int k = 0; k < 5; k++){
        int i0 = (2*k) * 32 + lane;
        stg[(i0 / 18) * 40 + (i0 % 18)] = __ushort_as_half((unsigned short)(ps[k] & 0xffffu));
        if (k < 4){
            int i1 = i0 + 32;
            stg[(i1 / 18) * 40 + (i1 % 18)] = __ushort_as_half((unsigned short)(ps[k] >> 16));
        }
    }
    #pragma unroll
    for (int k = 0; k < 3; k++){
        int i0 = (2*k) * 32 + lane, i1 = i0 + 32;
        int r0 = (i0 / 96) * 8 + (i0 / 12) % 8, c0 = 18 + i0 % 12;
        int r1 = (i1 / 96) * 8 + (i1 / 12) % 8, c1 = 18 + i1 % 12;
        stg[r0 * 40 + c0] = __ushort_as_half((unsigned short)(pn[k] & 0xffffu));
        stg[r1 * 40 + c1] = __ushort_as_half((unsigned short)(pn[k] >> 16));
    }
}

// attention weights from e-frags of one slab (chunked, low reg pressure)
__device__ __forceinline__ void attn_w8(const uint32_t af[8][4], float qs,
                                        float& wA, float& wB){
    float sA = 0.f, sB = 0.f;
    #pragma unroll
    for (int c = 0; c < 4; c++){
        float oa[8], fb[8];
        {
            float2 u0 = __half22float2(*(__half2*)&af[2*c][0]);
            float2 u2 = __half22float2(*(__half2*)&af[2*c][2]);
            float2 u4 = __half22float2(*(__half2*)&af[2*c+1][0]);
            float2 u6 = __half22float2(*(__half2*)&af[2*c+1][2]);
            oa[0]=u0.x; oa[1]=u0.y; oa[2]=u2.x; oa[3]=u2.y;
            oa[4]=u4.x; oa[5]=u4.y; oa[6]=u6.x; oa[7]=u6.y;
        }
        #pragma unroll
        for (int i = 0; i < 8; i++) fb[i] = oa[i];
        #pragma unroll
        for (int o = 4; o <= 16; o <<= 1)
            #pragma unroll
            for (int i = 0; i < 8; i++) fb[i] += __shfl_xor_sync(0xffffffff, fb[i], o);
        #pragma unroll
        for (int i = 0; i < 8; i++) sA = fmaf(fb[i], oa[i], sA);
        {
            float2 u1 = __half22float2(*(__half2*)&af[2*c][1]);
            float2 u3 = __half22float2(*(__half2*)&af[2*c][3]);
            float2 u5 = __half22float2(*(__half2*)&af[2*c+1][1]);
            float2 u7 = __half22float2(*(__half2*)&af[2*c+1][3]);
            oa[0]=u1.x; oa[1]=u1.y; oa[2]=u3.x; oa[3]=u3.y;
            oa[4]=u5.x; oa[5]=u5.y; oa[6]=u7.x; oa[7]=u7.y;
        }
        #pragma unroll
        for (int i = 0; i < 8; i++) fb[i] = oa[i];
        #pragma unroll
        for (int o = 4; o <= 16; o <<= 1)
            #pragma unroll
            for (int i = 0; i < 8; i++) fb[i] += __shfl_xor_sync(0xffffffff, fb[i], o);
        #pragma unroll
        for (int i = 0; i < 8; i++) sB = fmaf(fb[i], oa[i], sB);
    }
    sA *= qs; sB *= qs;
    sA += __shfl_xor_sync(0xffffffff, sA, 1);
    sA += __shfl_xor_sync(0xffffffff, sA, 2);
    sB += __shfl_xor_sync(0xffffffff, sB, 1);
    sB += __shfl_xor_sync(0xffffffff, sB, 2);
    float mxA = sA, mxB = sB;
    #pragma unroll
    for (int o = 4; o <= 16; o <<= 1){
        mxA = fmaxf(mxA, __shfl_xor_sync(0xffffffff, mxA, o));
        mxB = fmaxf(mxB, __shfl_xor_sync(0xffffffff, mxB, o));
    }
    float eA = __expf(sA - mxA), eB = __expf(sB - mxB);
    float uA = eA, uB = eB;
    #pragma unroll
    for (int o = 4; o <= 16; o <<= 1){
        uA += __shfl_xor_sync(0xffffffff, uA, o);
        uB += __shfl_xor_sync(0xffffffff, uB, o);
    }
    wA = __fdividef(eA, uA); wB = __fdividef(eB, uB);
}

// smem offsets (fused)
#define F_W1E  0
#define F_W2E  8192
#define F_W1V  40960
#define F_W2V  73728
#define F_BS   106496
#define F_STG  108544
#define F_SMEM (108544 + 12 * 16 * 40 * 2)   // 123904

// ============================================================================
// FUSED: gather -> embed MLP -> attn -> value MLP -> combine -> AA.
// 384 threads (12 warps); each warp owns a PAIR of 16-row slabs (4 batches),
// layers run in column-quarter passes (weight LDS per row halved).
// ============================================================================
__global__ void __launch_bounds__(384, 1)
fused_ev_kernel(const float* __restrict__ obs,
                const float* __restrict__ eW1, const float* __restrict__ eb1,
                const float* __restrict__ eW2, const float* __restrict__ eb2,
                const float* __restrict__ vW1, const float* __restrict__ vb1,
                const float* __restrict__ vW2, const float* __restrict__ vb2,
                float* __restrict__ AA)
{
    extern __shared__ char sm[];
    uint4* W1E = (uint4*)(sm + F_W1E);
    uint4* W2E = (uint4*)(sm + F_W2E);
    uint4* W1V = (uint4*)(sm + F_W1V);
    uint4* W2V = (uint4*)(sm + F_W2V);
    float* bs  = (float*)(sm + F_BS);

    const int tid = threadIdx.x, w = tid >> 5, lane = tid & 31;
    const int t = lane & 3;

    pack_w4(eW1, W1E, 2, 30, tid, 384);
    pack_w4(eW2, W2E, 8, 128, tid, 384);
    pack_w4(vW1, W1V, 8, 128, tid, 384);
    pack_w4(vW2, W2V, 8, 128, tid, 384);
    if (tid < 128){
        bs[tid] = eb1[tid]; bs[128 + tid] = eb2[tid];
        bs[256 + tid] = vb1[tid]; bs[384 + tid] = vb2[tid];
    }
    __syncthreads();

    __half* stg = (__half*)(sm + F_STG) + w * 16 * 40;
    const float qs = 0.011048543456039806f;   // 1/(8*sqrt(128))
    const int NPAIR = NROWS / 32;             // 16384
    const int step  = gridDim.x * 12;

    // zero pad cols 30,31 once
    if (lane < 16) *(uint32_t*)(stg + lane * 40 + 30) = 0u;
    __syncwarp();

    uint32_t ps[2][5], pn[2][3];
    int pair0 = blockIdx.x * 12 + w;
    if (pair0 < NPAIR){
        gather_pf(obs, pair0 * 2,     lane, ps[0], pn[0]);
        gather_pf(obs, pair0 * 2 + 1, lane, ps[1], pn[1]);
    }

    for (int pair = pair0; pair < NPAIR; pair += step){
        // ---- stage + extract L1 A-frags for both slabs ----
        uint32_t af1[2][2][4];
        #pragma unroll
        for (int s = 0; s < 2; s++){
            __syncwarp();
            stage_store(stg, lane, ps[s], pn[s]);
            __syncwarp();
            const __half* s0 = stg + (lane >> 2) * 40;
            const __half* s1 = s0 + 8 * 40;
            #pragma unroll
            for (int ks = 0; ks < 2; ks++){
                af1[s][ks][0] = *(const uint32_t*)(s0 + ks * 16 + 2 * t);
                af1[s][ks][1] = *(const uint32_t*)(s1 + ks * 16 + 2 * t);
                af1[s][ks][2] = *(const uint32_t*)(s0 + ks * 16 + 2 * t + 8);
                af1[s][ks][3] = *(const uint32_t*)(s1 + ks * 16 + 2 * t + 8);
            }
        }

        // ---- prefetch next pair (hidden by 4 MMA layers) ----
        if (pair + step < NPAIR){
            gather_pf(obs, (pair + step) * 2,     lane, ps[0], pn[0]);
            gather_pf(obs, (pair + step) * 2 + 1, lane, ps[1], pn[1]);
        }

        uint32_t afA[2][8][4], afB[2][8][4];
        layer_dual<2>(af1, W1E, afA, bs, t, lane);        // embed L1 -> h1
        layer_dual<8>(afA, W2E, afB, bs + 128, t, lane);  // embed L2 -> e (afB)

        float wA[2], wB[2];
        attn_w8(afB[0], qs, wA[0], wB[0]);
        attn_w8(afB[1], qs, wA[1], wB[1]);

        layer_dual<8>(afB, W1V, afA, bs + 256, t, lane);  // value L1 -> h2 (afA)
        layer_dual_combine(afA, W2V, bs + 384, wA, wB, AA, pair, t, lane);
    }
}

// smem offsets (agent)
#define A_W1   0
#define A_W2   32768
#define A_BS   65536
#define A_SMEM 66560

// ============================================================================
// Agent MLP (512 threads, single-slab register chain — unchanged from R14).
// ============================================================================
template<int KS>
__device__ __forceinline__ void mma_reg(const uint32_t af[][4], const uint4* __restrict__ Wp,
                                        float acc[16][4], int lane){
    #pragma unroll
    for (int nt = 0; nt < 16; nt++){ acc[nt][0]=acc[nt][1]=acc[nt][2]=acc[nt][3]=0.f; }
    #pragma unroll
    for (int ks = 0; ks < KS; ks++){
        #pragma unroll
        for (int ntp = 0; ntp < 8; ntp++){
            uint4 b = Wp[ks * 256 + ntp * 32 + lane];
            mma16(acc[2*ntp],   af[ks][0], af[ks][1], af[ks][2], af[ks][3], b.x, b.y);
            mma16(acc[2*ntp+1], af[ks][0], af[ks][1], af[ks][2], af[ks][3], b.z, b.w);
        }
    }
}

__device__ __forceinline__ void transition(const float acc[16][4], uint32_t af[8][4],
                                           const float* __restrict__ bias, int t){
    #pragma unroll
    for (int ks = 0; ks < 8; ks++){
        int c0 = (2*ks) * 8 + 2 * t, c1 = c0 + 8;
        float b00 = bias[c0], b01 = bias[c0 + 1];
        float b10 = bias[c1], b11 = bias[c1 + 1];
        af[ks][0] = pack2(fast_tanh(acc[2*ks][0] + b00),   fast_tanh(acc[2*ks][1] + b01));
        af[ks][1] = pack2(fast_tanh(acc[2*ks][2] + b00),   fast_tanh(acc[2*ks][3] + b01));
        af[ks][2] = pack2(fast_tanh(acc[2*ks+1][0] + b10), fast_tanh(acc[2*ks+1][1] + b11));
        af[ks][3] = pack2(fast_tanh(acc[2*ks+1][2] + b10), fast_tanh(acc[2*ks+1][3] + b11));
    }
}

__global__ void __launch_bounds__(512, 1)
agent_kernel(const float* __restrict__ X,
             const float* __restrict__ W1, const float* __restrict__ b1,
             const float* __restrict__ W2, const float* __restrict__ b2,
             __half* __restrict__ Y)
{
    extern __shared__ char sm[];
    uint4* Wp1 = (uint4*)(sm + A_W1);
    uint4* Wp2 = (uint4*)(sm + A_W2);
    float* bs  = (float*)(sm + A_BS);

    const int tid = threadIdx.x, w = tid >> 5, lane = tid & 31;
    const int g = lane >> 2, t = lane & 3;

    pack_w4(W1, Wp1, 8, 128, tid, 512);
    pack_w4(W2, Wp2, 8, 128, tid, 512);
    if (tid < 128){ bs[tid] = b1[tid]; bs[128 + tid] = b2[tid]; }
    __syncthreads();

    const int NSLAB = BATCHN / 16;            // 4096
    const int step  = gridDim.x * 16;

    for (int slab = blockIdx.x * 16 + w; slab < NSLAB; slab += step){
        const int row0 = slab * 16;
        uint32_t af[8][4];
        {
            const float2* pA = (const float2*)(X + (size_t)(row0 + g) * 128);
            const float2* pB = (const float2*)(X + (size_t)(row0 + g + 8) * 128);
            #pragma unroll
            for (int ks = 0; ks < 8; ks++){
                float2 a0 = pA[ks * 8 + t],     b0v = pB[ks * 8 + t];
                float2 a2 = pA[ks * 8 + t + 4], b2v = pB[ks * 8 + t + 4];
                af[ks][0] = pack2(a0.x, a0.y);
                af[ks][1] = pack2(b0v.x, b0v.y);
                af[ks][2] = pack2(a2.x, a2.y);
                af[ks][3] = pack2(b2v.x, b2v.y);
            }
        }
        float acc[16][4];
        mma_reg<8>(af, Wp1, acc, lane);
        transition(acc, af, bs, t);
        mma_reg<8>(af, Wp2, acc, lane);
        {
            __half* y0 = Y + (size_t)(row0 + g) * 128;
            __half* y1 = Y + (size_t)(row0 + g + 8) * 128;
            #pragma unroll
            for (int nt = 0; nt < 16; nt++){
                int c = nt * 8 + 2 * t;
                float b0 = bs[128 + c], b1v = bs[128 + c + 1];
                *(__half2*)(y0 + c) = __floats2half2_rn(tanh_acc(acc[nt][0] + b0),
                                                        tanh_acc(acc[nt][1] + b1v));
                *(__half2*)(y1 + c) = __floats2half2_rn(tanh_acc(acc[nt][2] + b0),
                                                        tanh_acc(acc[nt][3] + b1v));
            }
        }
    }
}

// ============================================================================
// Per-group multi-head attention (8 heads x 16 dims over 8 agents) + tile x8.
// ============================================================================
__global__ void __launch_bounds__(128)
mha_kernel(const float* __restrict__ AA, const __half* __restrict__ AV,
           float* __restrict__ out)
{
    __shared__ float ks[8][128];
    __shared__ float vs[8][128];
    const int g = blockIdx.x;
    const int j = threadIdx.x;
    const size_t base = (size_t)g * 8 * 128;

    #pragma unroll
    for (int a = 0; a < 8; a++){
        ks[a][j] = AA[base + a * 128 + j];
        vs[a][j] = __half2float(AV[base + a * 128 + j]);
    }
    __syncthreads();

    float q = 0.0f;
    #pragma unroll
    for (int a = 0; a < 8; a++) q += ks[a][j];
    q *= 0.03125f;                            // mean(1/8) * rsqrt(16)

    float s[8];
    #pragma unroll
    for (int a = 0; a < 8; a++){
        float p = q * ks[a][j];
        p += __shfl_xor_sync(0xffffffff, p, 8);
        p += __shfl_xor_sync(0xffffffff, p, 4);
        p += __shfl_xor_sync(0xffffffff, p, 2);
        p += __shfl_xor_sync(0xffffffff, p, 1);
        s[a] = p;
    }
    float mx = s[0];
    #pragma unroll
    for (int a = 1; a < 8; a++) mx = fmaxf(mx, s[a]);
    float wv[8], wsum = 0.0f;
    #pragma unroll
    for (int a = 0; a < 8; a++){ wv[a] = __expf(s[a] - mx); wsum += wv[a]; }
    const float inv = 1.0f / wsum;

    float o = 0.0f;
    #pragma unroll
    for (int a = 0; a < 8; a++) o += wv[a] * vs[a][j];
    o *= inv;

    #pragma unroll
    for (int tt = 0; tt < 8; tt++)
        out[((size_t)(tt * NGRP + g)) * 128 + j] = o;
}

// ============================================================================
extern "C" void kernel_launch(void* const* d_in, const int* in_sizes, int n_in,
                              void* d_out, int out_size)
{
    const float* obs = (const float*)d_in[0];
    const float* eW1 = (const float*)d_in[1];
    const float* eb1 = (const float*)d_in[2];
    const float* eW2 = (const float*)d_in[3];
    const float* eb2 = (const float*)d_in[4];
    const float* vW1 = (const float*)d_in[5];
    const float* vb1 = (const float*)d_in[6];
    const float* vW2 = (const float*)d_in[7];
    const float* vb2 = (const float*)d_in[8];
    const float* aW1 = (const float*)d_in[9];
    const float* ab1 = (const float*)d_in[10];
    const float* aW2 = (const float*)d_in[11];
    const float* ab2 = (const float*)d_in[12];

    float* out = (float*)d_out;                 // multi_head_attention
    float* AA  = out + (size_t)BATCHN * 128;    // agent_attention

    void* pav; cudaGetSymbolAddress(&pav, g_av);
    __half* av_g = (__half*)pav;

    cudaFuncSetAttribute(fused_ev_kernel, cudaFuncAttributeMaxDynamicSharedMemorySize, F_SMEM);
    cudaFuncSetAttribute(agent_kernel,    cudaFuncAttributeMaxDynamicSharedMemorySize, A_SMEM);

    fused_ev_kernel<<<148, 384, F_SMEM>>>(obs, eW1, eb1, eW2, eb2,
                                          vW1, vb1, vW2, vb2, AA);
    agent_kernel<<<148, 512, A_SMEM>>>(AA, aW1, ab1, aW2, ab2, av_g);
    mha_kernel<<<NGRP, 128>>>(AA, av_g, out);
}

// round 17
// speedup vs baseline: 1.1441x; 1.1441x over previous
#include <cuda_runtime.h>
#include <cuda_fp16.h>
#include <stdint.h>

#define BATCHN 65536
#define NROWS  (BATCHN * 8)
#define NGRP   8192
#define OBSD   114

__device__ __half g_av[(size_t)BATCHN * 128];   // agent values, fp16 (16 MB)

__device__ __forceinline__ float fast_tanh(float x){float y;asm("tanh.approx.f32 %0,%1;":"=f"(y):"f"(x));return y;}
__device__ __forceinline__ float tanh_acc(float x){ return 1.f - __fdividef(2.f, __expf(2.f * x) + 1.f); }
__device__ __forceinline__ uint32_t pack2(float a, float b){ __half2 h = __floats2half2_rn(a, b); return *(uint32_t*)&h; }

__device__ __forceinline__ void mma16(float c[4], uint32_t a0, uint32_t a1, uint32_t a2, uint32_t a3,
                                      uint32_t b0, uint32_t b1){
    asm volatile("mma.sync.aligned.m16n8k16.row.col.f32.f16.f16.f32 "
                 "{%0,%1,%2,%3},{%4,%5,%6,%7},{%8,%9},{%0,%1,%2,%3};"
                 : "+f"(c[0]), "+f"(c[1]), "+f"(c[2]), "+f"(c[3])
                 : "r"(a0), "r"(a1), "r"(a2), "r"(a3), "r"(b0), "r"(b1));
}

// Full-width layer: warp's 16 rows x 128 cols. A-fragments af[ks][4] in regs.
template<int KS>
__device__ __forceinline__ void mma_reg(const uint32_t af[][4], const uint4* __restrict__ Wp,
                                        float acc[16][4], int lane){
    #pragma unroll
    for (int nt = 0; nt < 16; nt++){ acc[nt][0]=acc[nt][1]=acc[nt][2]=acc[nt][3]=0.f; }
    #pragma unroll
    for (int ks = 0; ks < KS; ks++){
        #pragma unroll
        for (int ntp = 0; ntp < 8; ntp++){
            uint4 b = Wp[ks * 256 + ntp * 32 + lane];
            mma16(acc[2*ntp],   af[ks][0], af[ks][1], af[ks][2], af[ks][3], b.x, b.y);
            mma16(acc[2*ntp+1], af[ks][0], af[ks][1], af[ks][2], af[ks][3], b.z, b.w);
        }
    }
}

// acc(+bias) -> fast tanh -> repack as next layer's A-fragments (in registers).
__device__ __forceinline__ void transition(const float acc[16][4], uint32_t af[8][4],
                                           const float* __restrict__ bias, int t){
    #pragma unroll
    for (int ks = 0; ks < 8; ks++){
        int c0 = (2*ks) * 8 + 2 * t, c1 = c0 + 8;
        float b00 = bias[c0], b01 = bias[c0 + 1];
        float b10 = bias[c1], b11 = bias[c1 + 1];
        af[ks][0] = pack2(fast_tanh(acc[2*ks][0] + b00),   fast_tanh(acc[2*ks][1] + b01));
        af[ks][1] = pack2(fast_tanh(acc[2*ks][2] + b00),   fast_tanh(acc[2*ks][3] + b01));
        af[ks][2] = pack2(fast_tanh(acc[2*ks+1][0] + b10), fast_tanh(acc[2*ks+1][1] + b11));
        af[ks][3] = pack2(fast_tanh(acc[2*ks+1][2] + b10), fast_tanh(acc[2*ks+1][3] + b11));
    }
}

// Pack W[k][n] (row-major K x 128 fp32) into uint4 B-fragment-pair order.
__device__ __forceinline__ void pack_w4(const float* __restrict__ W, uint4* __restrict__ Wp,
                                        int KS, int K, int tid, int nthr){
    for (int f = tid; f < KS * 8 * 32; f += nthr){
        int ks = f >> 8, ntp = (f >> 5) & 7, lane = f & 31;
        int g = lane >> 2, t = lane & 3;
        int n0 = ntp * 16 + g, n1 = n0 + 8;
        int k0 = ks * 16 + 2 * t, k1 = k0 + 8;
        float a00 = (k0     < K) ? W[(size_t)k0       * 128 + n0] : 0.f;
        float a01 = (k0 + 1 < K) ? W[(size_t)(k0 + 1) * 128 + n0] : 0.f;
        float a10 = (k1     < K) ? W[(size_t)k1       * 128 + n0] : 0.f;
        float a11 = (k1 + 1 < K) ? W[(size_t)(k1 + 1) * 128 + n0] : 0.f;
        float b00 = (k0     < K) ? W[(size_t)k0       * 128 + n1] : 0.f;
        float b01 = (k0 + 1 < K) ? W[(size_t)(k0 + 1) * 128 + n1] : 0.f;
        float b10 = (k1     < K) ? W[(size_t)k1       * 128 + n1] : 0.f;
        float b11 = (k1 + 1 < K) ? W[(size_t)(k1 + 1) * 128 + n1] : 0.f;
        Wp[f] = make_uint4(pack2(a00, a01), pack2(a10, a11), pack2(b00, b01), pack2(b10, b11));
    }
}

// ---- Coalesced gather prefetch ----
__device__ __forceinline__ void gather_pf(const float* __restrict__ obs, int slab, int lane,
                                          uint32_t ps[5], uint32_t pn[3]){
    const int base = slab * 16;
    #pragma unroll
    for (int k = 0; k < 4; k++){
        int i0 = (2*k) * 32 + lane, i1 = i0 + 32;
        float v0 = obs[(size_t)((base + i0 / 18) & (BATCHN - 1)) * OBSD + i0 % 18];
        float v1 = obs[(size_t)((base + i1 / 18) & (BATCHN - 1)) * OBSD + i1 % 18];
        ps[k] = pack2(v0, v1);
    }
    {
        int i0 = 8 * 32 + lane;
        float v0 = obs[(size_t)((base + i0 / 18) & (BATCHN - 1)) * OBSD + i0 % 18];
        ps[4] = pack2(v0, 0.f);
    }
    const float* nb = obs + (size_t)(slab * 2) * OBSD + 18;
    #pragma unroll
    for (int k = 0; k < 3; k++){
        int i0 = (2*k) * 32 + lane, i1 = i0 + 32;
        float v0 = (i0 < 96) ? nb[i0] : nb[OBSD + (i0 - 96)];
        float v1 = (i1 < 96) ? nb[i1] : nb[OBSD + (i1 - 96)];
        pn[k] = pack2(v0, v1);
    }
}

// Store prefetched values into the 16x40-half stage (scattered STS.16).
__device__ __forceinline__ void stage_store(__half* __restrict__ stg, int lane,
                                            const uint32_t ps[5], const uint32_t pn[3]){
    #pragma unroll
    for (int k = 0; k < 5; k++){
        int i0 = (2*k) * 32 + lane;
        stg[(i0 / 18) * 40 + (i0 % 18)] = __ushort_as_half((unsigned short)(ps[k] & 0xffffu));
        if (k < 4){
            int i1 = i0 + 32;
            stg[(i1 / 18) * 40 + (i1 % 18)] = __ushort_as_half((unsigned short)(ps[k] >> 16));
        }
    }
    #pragma unroll
    for (int k = 0; k < 3; k++){
        int i0 = (2*k) * 32 + lane, i1 = i0 + 32;
        int r0 = (i0 / 96) * 8 + (i0 / 12) % 8, c0 = 18 + i0 % 12;
        int r1 = (i1 / 96) * 8 + (i1 / 12) % 8, c1 = 18 + i1 % 12;
        stg[r0 * 40 + c0] = __ushort_as_half((unsigned short)(pn[k] & 0xffffu));
        stg[r1 * 40 + c1] = __ushort_as_half((unsigned short)(pn[k] >> 16));
    }
}

// smem offsets (fused)
#define F_W1E  0
#define F_W2E  8192
#define F_W1V  40960
#define F_W2V  73728
#define F_BS   106496
#define F_STG  108544
#define F_SMEM (108544 + 16 * 16 * 40 * 2)   // 129024

// ============================================================================
// FUSED: gather -> embed MLP -> attn -> value MLP -> combine -> AA.
// 512 threads (16 warps, 4/SMSP, RF exactly full at 128 regs).
// ============================================================================
__global__ void __launch_bounds__(512, 1)
fused_ev_kernel(const float* __restrict__ obs,
                const float* __restrict__ eW1, const float* __restrict__ eb1,
                const float* __restrict__ eW2, const float* __restrict__ eb2,
                const float* __restrict__ vW1, const float* __restrict__ vb1,
                const float* __restrict__ vW2, const float* __restrict__ vb2,
                float* __restrict__ AA)
{
    extern __shared__ char sm[];
    uint4* W1E = (uint4*)(sm + F_W1E);
    uint4* W2E = (uint4*)(sm + F_W2E);
    uint4* W1V = (uint4*)(sm + F_W1V);
    uint4* W2V = (uint4*)(sm + F_W2V);
    float* bs  = (float*)(sm + F_BS);

    const int tid = threadIdx.x, w = tid >> 5, lane = tid & 31;
    const int g = lane >> 2, t = lane & 3;

    pack_w4(eW1, W1E, 2, 30, tid, 512);
    pack_w4(eW2, W2E, 8, 128, tid, 512);
    pack_w4(vW1, W1V, 8, 128, tid, 512);
    pack_w4(vW2, W2V, 8, 128, tid, 512);
    if (tid < 128){
        bs[tid] = eb1[tid]; bs[128 + tid] = eb2[tid];
        bs[256 + tid] = vb1[tid]; bs[384 + tid] = vb2[tid];
    }
    __syncthreads();

    __half* stg = (__half*)(sm + F_STG) + w * 16 * 40;
    const float qs = 0.011048543456039806f;   // 1/(8*sqrt(128))
    const int NSLAB = NROWS / 16;             // 32768
    const int step  = gridDim.x * 16;

    // zero pad cols 30,31 once (never overwritten; frag cols 30,31 read them)
    if (lane < 16) *(uint32_t*)(stg + lane * 40 + 30) = 0u;
    __syncwarp();

    uint32_t ps[5], pn[3];
    int slab0 = blockIdx.x * 16 + w;
    if (slab0 < NSLAB) gather_pf(obs, slab0, lane, ps, pn);

    for (int slab = slab0; slab < NSLAB; slab += step){
        __syncwarp();   // prior iteration's stage reads complete
        stage_store(stg, lane, ps, pn);
        __syncwarp();

        // ---- embed L1 (K=32): A-frags from stage ----
        uint32_t af1[2][4];
        {
            const __half* s0 = stg + g * 40;
            const __half* s1 = stg + (g + 8) * 40;
            #pragma unroll
            for (int ks = 0; ks < 2; ks++){
                af1[ks][0] = *(const uint32_t*)(s0 + ks * 16 + 2 * t);
                af1[ks][1] = *(const uint32_t*)(s1 + ks * 16 + 2 * t);
                af1[ks][2] = *(const uint32_t*)(s0 + ks * 16 + 2 * t + 8);
                af1[ks][3] = *(const uint32_t*)(s1 + ks * 16 + 2 * t + 8);
            }
        }

        // ---- prefetch next slab (LDG latency hidden by 4 MMA layers) ----
        if (slab + step < NSLAB) gather_pf(obs, slab + step, lane, ps, pn);

        float acc[16][4];
        uint32_t af[8][4];
        mma_reg<2>(af1, W1E, acc, lane);
        transition(acc, af, bs, t);            // h1 -> af
        mma_reg<8>(af, W2E, acc, lane);        // embed L2
        transition(acc, af, bs + 128, t);      // e -> af (fp16, stays in regs)

        // ---- attention weights from e: chunked g-dim reduction ----
        float wA, wB;
        {
            float sA = 0.f, sB = 0.f;
            #pragma unroll
            for (int c = 0; c < 4; c++){
                float oa[8], fb[8];
                {
                    float2 u0 = __half22float2(*(__half2*)&af[2*c][0]);
                    float2 u2 = __half22float2(*(__half2*)&af[2*c][2]);
                    float2 u4 = __half22float2(*(__half2*)&af[2*c+1][0]);
                    float2 u6 = __half22float2(*(__half2*)&af[2*c+1][2]);
                    oa[0]=u0.x; oa[1]=u0.y; oa[2]=u2.x; oa[3]=u2.y;
                    oa[4]=u4.x; oa[5]=u4.y; oa[6]=u6.x; oa[7]=u6.y;
                }
                #pragma unroll
                for (int i = 0; i < 8; i++) fb[i] = oa[i];
                #pragma unroll
                for (int o = 4; o <= 16; o <<= 1)
                    #pragma unroll
                    for (int i = 0; i < 8; i++) fb[i] += __shfl_xor_sync(0xffffffff, fb[i], o);
                #pragma unroll
                for (int i = 0; i < 8; i++) sA = fmaf(fb[i], oa[i], sA);
                {
                    float2 u1 = __half22float2(*(__half2*)&af[2*c][1]);
                    float2 u3 = __half22float2(*(__half2*)&af[2*c][3]);
                    float2 u5 = __half22float2(*(__half2*)&af[2*c+1][1]);
                    float2 u7 = __half22float2(*(__half2*)&af[2*c+1][3]);
                    oa[0]=u1.x; oa[1]=u1.y; oa[2]=u3.x; oa[3]=u3.y;
                    oa[4]=u5.x; oa[5]=u5.y; oa[6]=u7.x; oa[7]=u7.y;
                }
                #pragma unroll
                for (int i = 0; i < 8; i++) fb[i] = oa[i];
                #pragma unroll
                for (int o = 4; o <= 16; o <<= 1)
                    #pragma unroll
                    for (int i = 0; i < 8; i++) fb[i] += __shfl_xor_sync(0xffffffff, fb[i], o);
                #pragma unroll
                for (int i = 0; i < 8; i++) sB = fmaf(fb[i], oa[i], sB);
            }
            sA *= qs; sB *= qs;
            sA += __shfl_xor_sync(0xffffffff, sA, 1);
            sA += __shfl_xor_sync(0xffffffff, sA, 2);
            sB += __shfl_xor_sync(0xffffffff, sB, 1);
            sB += __shfl_xor_sync(0xffffffff, sB, 2);
            float mxA = sA, mxB = sB;
            #pragma unroll
            for (int o = 4; o <= 16; o <<= 1){
                mxA = fmaxf(mxA, __shfl_xor_sync(0xffffffff, mxA, o));
                mxB = fmaxf(mxB, __shfl_xor_sync(0xffffffff, mxB, o));
            }
            float eA = __expf(sA - mxA), eB = __expf(sB - mxB);
            float uA = eA, uB = eB;
            #pragma unroll
            for (int o = 4; o <= 16; o <<= 1){
                uA += __shfl_xor_sync(0xffffffff, uA, o);
                uB += __shfl_xor_sync(0xffffffff, uB, o);
            }
            wA = __fdividef(eA, uA); wB = __fdividef(eB, uB);
        }

        // ---- value MLP on e ----
        mma_reg<8>(af, W1V, acc, lane);
        transition(acc, af, bs + 256, t);      // h2 -> af
        mma_reg<8>(af, W2V, acc, lane);

        // ---- v = tanh_acc(acc+b2); weighted sum over neighbors (g-dim) -> AA ----
        #pragma unroll
        for (int nt = 0; nt < 16; nt++){
            int c = nt * 8 + 2 * t;
            float b0 = bs[384 + c], b1 = bs[384 + c + 1];
            acc[nt][0] = tanh_acc(acc[nt][0] + b0) * wA;
            acc[nt][1] = tanh_acc(acc[nt][1] + b1) * wA;
            acc[nt][2] = tanh_acc(acc[nt][2] + b0) * wB;
            acc[nt][3] = tanh_acc(acc[nt][3] + b1) * wB;
        }
        #pragma unroll
        for (int o = 4; o <= 16; o <<= 1)
            #pragma unroll
            for (int nt = 0; nt < 16; nt++){
                acc[nt][0] += __shfl_xor_sync(0xffffffff, acc[nt][0], o);
                acc[nt][1] += __shfl_xor_sync(0xffffffff, acc[nt][1], o);
                acc[nt][2] += __shfl_xor_sync(0xffffffff, acc[nt][2], o);
                acc[nt][3] += __shfl_xor_sync(0xffffffff, acc[nt][3], o);
            }
        float* outA = AA + (size_t)(slab * 2) * 128;
        if (lane < 4){
            #pragma unroll
            for (int nt = 0; nt < 16; nt++)
                *(float2*)(outA + nt * 8 + 2 * t) = make_float2(acc[nt][0], acc[nt][1]);
        } else if (lane < 8){
            #pragma unroll
            for (int nt = 0; nt < 16; nt++)
                *(float2*)(outA + 128 + nt * 8 + 2 * t) = make_float2(acc[nt][2], acc[nt][3]);
        }
    }
}

// smem offsets (agent)
#define A_W1   0
#define A_W2   32768
#define A_BS   65536
#define A_SMEM 66560

// ============================================================================
// Agent MLP: AA (fp32) -> tanh(128->128) -> tanh(128->128) -> g_av (fp16)
// ============================================================================
__global__ void __launch_bounds__(512, 1)
agent_kernel(const float* __restrict__ X,
             const float* __restrict__ W1, const float* __restrict__ b1,
             const float* __restrict__ W2, const float* __restrict__ b2,
             __half* __restrict__ Y)
{
    extern __shared__ char sm[];
    uint4* Wp1 = (uint4*)(sm + A_W1);
    uint4* Wp2 = (uint4*)(sm + A_W2);
    float* bs  = (float*)(sm + A_BS);

    const int tid = threadIdx.x, w = tid >> 5, lane = tid & 31;
    const int g = lane >> 2, t = lane & 3;

    pack_w4(W1, Wp1, 8, 128, tid, 512);
    pack_w4(W2, Wp2, 8, 128, tid, 512);
    if (tid < 128){ bs[tid] = b1[tid]; bs[128 + tid] = b2[tid]; }
    __syncthreads();

    const int NSLAB = BATCHN / 16;            // 4096
    const int step  = gridDim.x * 16;

    for (int slab = blockIdx.x * 16 + w; slab < NSLAB; slab += step){
        const int row0 = slab * 16;
        uint32_t af[8][4];
        {
            const float2* pA = (const float2*)(X + (size_t)(row0 + g) * 128);
            const float2* pB = (const float2*)(X + (size_t)(row0 + g + 8) * 128);
            #pragma unroll
            for (int ks = 0; ks < 8; ks++){
                float2 a0 = pA[ks * 8 + t],     b0v = pB[ks * 8 + t];
                float2 a2 = pA[ks * 8 + t + 4], b2v = pB[ks * 8 + t + 4];
                af[ks][0] = pack2(a0.x, a0.y);
                af[ks][1] = pack2(b0v.x, b0v.y);
                af[ks][2] = pack2(a2.x, a2.y);
                af[ks][3] = pack2(b2v.x, b2v.y);
            }
        }
        float acc[16][4];
        mma_reg<8>(af, Wp1, acc, lane);
        transition(acc, af, bs, t);
        mma_reg<8>(af, Wp2, acc, lane);
        {
            __half* y0 = Y + (size_t)(row0 + g) * 128;
            __half* y1 = Y + (size_t)(row0 + g + 8) * 128;
            #pragma unroll
            for (int nt = 0; nt < 16; nt++){
                int c = nt * 8 + 2 * t;
                float b0 = bs[128 + c], b1v = bs[128 + c + 1];
                *(__half2*)(y0 + c) = __floats2half2_rn(tanh_acc(acc[nt][0] + b0),
                                                        tanh_acc(acc[nt][1] + b1v));
                *(__half2*)(y1 + c) = __floats2half2_rn(tanh_acc(acc[nt][2] + b0),
                                                        tanh_acc(acc[nt][3] + b1v));
            }
        }
    }
}

// ============================================================================
// Per-group multi-head attention (8 heads x 16 dims over 8 agents) + tile x8.
// ============================================================================
__global__ void __launch_bounds__(128)
mha_kernel(const float* __restrict__ AA, const __half* __restrict__ AV,
           float* __restrict__ out)
{
    __shared__ float ks[8][128];
    __shared__ float vs[8][128];
    const int g = blockIdx.x;
    const int j = threadIdx.x;
    const size_t base = (size_t)g * 8 * 128;

    #pragma unroll
    for (int a = 0; a < 8; a++){
        ks[a][j] = AA[base + a * 128 + j];
        vs[a][j] = __half2float(AV[base + a * 128 + j]);
    }
    __syncthreads();

    float q = 0.0f;
    #pragma unroll
    for (int a = 0; a < 8; a++) q += ks[a][j];
    q *= 0.03125f;                            // mean(1/8) * rsqrt(16)

    float s[8];
    #pragma unroll
    for (int a = 0; a < 8; a++){
        float p = q * ks[a][j];
        p += __shfl_xor_sync(0xffffffff, p, 8);
        p += __shfl_xor_sync(0xffffffff, p, 4);
        p += __shfl_xor_sync(0xffffffff, p, 2);
        p += __shfl_xor_sync(0xffffffff, p, 1);
        s[a] = p;
    }
    float mx = s[0];
    #pragma unroll
    for (int a = 1; a < 8; a++) mx = fmaxf(mx, s[a]);
    float wv[8], wsum = 0.0f;
    #pragma unroll
    for (int a = 0; a < 8; a++){ wv[a] = __expf(s[a] - mx); wsum += wv[a]; }
    const float inv = 1.0f / wsum;

    float o = 0.0f;
    #pragma unroll
    for (int a = 0; a < 8; a++) o += wv[a] * vs[a][j];
    o *= inv;

    #pragma unroll
    for (int tt = 0; tt < 8; tt++)
        out[((size_t)(tt * NGRP + g)) * 128 + j] = o;
}

// ============================================================================
extern "C" void kernel_launch(void* const* d_in, const int* in_sizes, int n_in,
                              void* d_out, int out_size)
{
    const float* obs = (const float*)d_in[0];
    const float* eW1 = (const float*)d_in[1];
    const float* eb1 = (const float*)d_in[2];
    const float* eW2 = (const float*)d_in[3];
    const float* eb2 = (const float*)d_in[4];
    const float* vW1 = (const float*)d_in[5];
    const float* vb1 = (const float*)d_in[6];
    const float* vW2 = (const float*)d_in[7];
    const float* vb2 = (const float*)d_in[8];
    const float* aW1 = (const float*)d_in[9];
    const float* ab1 = (const float*)d_in[10];
    const float* aW2 = (const float*)d_in[11];
    const float* ab2 = (const float*)d_in[12];

    float* out = (float*)d_out;                 // multi_head_attention
    float* AA  = out + (size_t)BATCHN * 128;    // agent_attention

    void* pav; cudaGetSymbolAddress(&pav, g_av);
    __half* av_g = (__half*)pav;

    cudaFuncSetAttribute(fused_ev_kernel, cudaFuncAttributeMaxDynamicSharedMemorySize, F_SMEM);
    cudaFuncSetAttribute(agent_kernel,    cudaFuncAttributeMaxDynamicSharedMemorySize, A_SMEM);

    fused_ev_kernel<<<148, 512, F_SMEM>>>(obs, eW1, eb1, eW2, eb2,
                                          vW1, vb1, vW2, vb2, AA);
    agent_kernel<<<148, 512, A_SMEM>>>(AA, aW1, ab1, aW2, ab2, av_g);
    mha_kernel<<<NGRP, 128>>>(AA, av_g, out);
}